// round 12
// baseline (speedup 1.0000x reference)
#include <cuda_runtime.h>
#include <cuda_bf16.h>
#include <cstdint>

// Problem dims
#define MB   16384   // batch
#define K1   2048    // IN_DIM
#define N1   8192    // HV_DIM
#define NC   1000    // NUM_CLASSES
#define NCP  1024    // padded classes

// int8 GEMM tiles: BK=128 int8 -> 128B SW128 rows (same byte geometry as before)
#define G1_BM  128
#define G1_BN  128
#define G1_BK  128
#define G1_A0_OFF   0            // hi limb 128x128B = 16KB
#define G1_A1_OFF   16384        // lo limb
#define G1_B_OFF    32768        // B 128x128B = 16KB
#define G1_STAGE    49152
#define G1_SMEM     (3 * G1_STAGE)   // 147456

#define G2_BM  128
#define G2_BN  256
#define G2_BK  128
#define G2_A_OFF    0            // 16KB
#define G2_B_OFF    16384        // 32KB
#define G2_STAGE    49152
#define G2_SMEM     (3 * G2_STAGE)   // 147456

#define ITAU    160              // |v| < ITAU (v = 4096*hv approx) -> fixup
#define WL_CAP  (1u << 22)

// -------------------- device scratch (allocation-free rule) -----------------
__device__ signed char g_xhi8[(size_t)MB * K1];
__device__ signed char g_xlo8[(size_t)MB * K1];
__device__ signed char g_projT8[(size_t)N1 * K1];     // [N1, K1] K-major s8
__device__ __nv_bfloat16 g_projT[(size_t)N1 * K1];    // bf16 copy for fixup
__device__ signed char g_hvb8[(size_t)MB * N1];       // hv_bin as s8
__device__ signed char g_chvT8[(size_t)NCP * N1];     // [NCP, N1] K-major s8
__device__ unsigned g_wl[WL_CAP];
__device__ unsigned g_wl_count;

// -------------------- PTX helpers (baseline ISA only) -----------------------
__device__ __forceinline__ uint32_t smem_u32(const void* p) {
    uint32_t a;
    asm("{ .reg .u64 t; cvta.to.shared.u64 t, %1; cvt.u32.u64 %0, t; }"
        : "=r"(a) : "l"(p));
    return a;
}
__device__ __forceinline__ void cp_async16(uint32_t dst, const void* src) {
    asm volatile("cp.async.cg.shared.global [%0], [%1], 16;\n"
                 :: "r"(dst), "l"(src) : "memory");
}
__device__ __forceinline__ void cp_commit() {
    asm volatile("cp.async.commit_group;" ::: "memory");
}
__device__ __forceinline__ void cp_wait1() {
    asm volatile("cp.async.wait_group 1;" ::: "memory");
}
__device__ __forceinline__ void cp_wait0() {
    asm volatile("cp.async.wait_group 0;" ::: "memory");
}
__device__ __forceinline__ void ldsm4(uint32_t& r0, uint32_t& r1, uint32_t& r2,
                                      uint32_t& r3, uint32_t addr) {
    asm volatile("ldmatrix.sync.aligned.m8n8.x4.shared.b16 {%0,%1,%2,%3}, [%4];"
                 : "=r"(r0), "=r"(r1), "=r"(r2), "=r"(r3) : "r"(addr));
}
// s8 IMMA, exact s32 accumulation
__device__ __forceinline__ void mma_s8(int* c, const uint32_t* a,
                                       const uint32_t* b) {
    asm volatile(
        "mma.sync.aligned.m16n8k32.row.col.s32.s8.s8.s32 "
        "{%0,%1,%2,%3}, {%4,%5,%6,%7}, {%8,%9}, {%0,%1,%2,%3};"
        : "+r"(c[0]), "+r"(c[1]), "+r"(c[2]), "+r"(c[3])
        : "r"(a[0]), "r"(a[1]), "r"(a[2]), "r"(a[3]), "r"(b[0]), "r"(b[1]));
}
__device__ __forceinline__ uint32_t swz(uint32_t off) {
    return off ^ ((off >> 3) & 0x70);
}

// ---------------------------------------------------------------------------
__global__ void zero_count_kernel() { g_wl_count = 0; }

// ---------------------------------------------------------------------------
// prep: fixed-point split  v = round(x*4096) = hi*256 + lo  (exact)
// ---------------------------------------------------------------------------
__global__ __launch_bounds__(256) void prep_split8(const float* __restrict__ x)
{
    size_t i4 = ((size_t)blockIdx.x * 256 + threadIdx.x) * 4;
    float4 v = *(const float4*)(x + i4);
    const float f[4] = {v.x, v.y, v.z, v.w};
    signed char h[4], l[4];
#pragma unroll
    for (int e = 0; e < 4; e++) {
        int vi = __float2int_rn(f[e] * 4096.0f);
        vi = max(-32512, min(32512, vi));
        int lo = (int)(signed char)(vi & 0xFF);
        int hi = (vi - lo) >> 8;              // in [-127, 127]
        h[e] = (signed char)hi;
        l[e] = (signed char)lo;
    }
    *(char4*)(g_xhi8 + i4) = make_char4(h[0], h[1], h[2], h[3]);
    *(char4*)(g_xlo8 + i4) = make_char4(l[0], l[1], l[2], l[3]);
}

// ---------------------------------------------------------------------------
// prep: projT (both s8 for GEMM and bf16 for fixup); proj is +/-1 (exact)
// ---------------------------------------------------------------------------
__global__ __launch_bounds__(256) void prep_projT_k(const float* __restrict__ proj)
{
    __shared__ float t[32][33];
    const int n0 = blockIdx.x * 32, k0 = blockIdx.y * 32;
    const int tx = threadIdx.x, ty = threadIdx.y;   // (32, 8)
#pragma unroll
    for (int i = 0; i < 4; i++)
        t[ty + i * 8][tx] = proj[(size_t)(k0 + ty + i * 8) * N1 + n0 + tx];
    __syncthreads();
#pragma unroll
    for (int i = 0; i < 4; i++) {
        int r = ty + i * 8;
        float v = t[tx][r];
        g_projT [(size_t)(n0 + r) * K1 + k0 + tx] = __float2bfloat16_rn(v);
        g_projT8[(size_t)(n0 + r) * K1 + k0 + tx] =
            (signed char)(v > 0.0f ? 1 : -1);
    }
}

// ---------------------------------------------------------------------------
// prep: chvT8[c][k] = s8(class_hv[k][c]), zero-padded classes 1000..1023
// ---------------------------------------------------------------------------
__global__ __launch_bounds__(256) void prep_chvT8(const float* __restrict__ chv)
{
    __shared__ float t[32][33];
    const int c0 = blockIdx.x * 32, k0 = blockIdx.y * 32;
    const int tx = threadIdx.x, ty = threadIdx.y;   // (32, 8)
#pragma unroll
    for (int i = 0; i < 4; i++) {
        int c = c0 + tx;
        t[ty + i * 8][tx] = (c < NC)
            ? chv[(size_t)(k0 + ty + i * 8) * NC + c] : 0.0f;
    }
    __syncthreads();
#pragma unroll
    for (int i = 0; i < 4; i++) {
        int r = ty + i * 8;
        float v = t[tx][r];
        g_chvT8[(size_t)(c0 + r) * N1 + k0 + tx] =
            (signed char)(v > 0.0f ? 1 : (v < 0.0f ? -1 : 0));
    }
}

// ---------------------------------------------------------------------------
// GEMM1 via s8 IMMA, 2 limbs (hi*256 + lo), exact s32 accumulation.
// CTA 128x128xK128; 8 warps (2m x 4n), warp tile 64x32; 3-stage cp.async.
// Epilogue: sign -> hv fp32 + g_hvb8 s8 + integer-borderline flagging.
// ---------------------------------------------------------------------------
__global__ __launch_bounds__(256, 1) void gemm1_imma(float* __restrict__ hv)
{
    extern __shared__ char smem[];
    const uint32_t sb = smem_u32(smem);
    const int tid = threadIdx.x, wid = tid >> 5, lane = tid & 31;
    const int warp_m = wid >> 2;        // 0..1 -> 64-row slab
    const int warp_n = wid & 3;         // 0..3 -> 32-col slab
    const int m0 = blockIdx.y * G1_BM;
    const int n0 = blockIdx.x * G1_BN;

    int chi[4][4][4], clo[4][4][4];
#pragma unroll
    for (int i = 0; i < 4; i++)
#pragma unroll
        for (int j = 0; j < 4; j++)
#pragma unroll
            for (int q = 0; q < 4; q++) { chi[i][j][q] = 0; clo[i][j][q] = 0; }

    auto load_stage = [&](int chunk, int s) {
        const size_t k0 = (size_t)chunk * G1_BK;     // bytes (1B/elem)
        const char* ah = (const char*)g_xhi8 + (size_t)m0 * K1 + k0;
        const char* al = (const char*)g_xlo8 + (size_t)m0 * K1 + k0;
        const char* bb = (const char*)g_projT8 + (size_t)n0 * K1 + k0;
#pragma unroll
        for (int i = 0; i < 4; i++) {
            int idx = tid + i * 256;                 // 0..1023
            int r = idx >> 3, cc = idx & 7;
            uint32_t so = swz((uint32_t)(r * 128 + cc * 16));
            size_t go = (size_t)r * K1 + cc * 16;
            cp_async16(sb + s * G1_STAGE + G1_A0_OFF + so, ah + go);
            cp_async16(sb + s * G1_STAGE + G1_A1_OFF + so, al + go);
            cp_async16(sb + s * G1_STAGE + G1_B_OFF  + so, bb + go);
        }
        cp_commit();
    };

    load_stage(0, 0);
    load_stage(1, 1);

    const int a_row = warp_m * 64 + (lane & 15);                 // + mt*16
    const int a_kc  = (lane >> 4);                               // 16B half
    const int b_row = warp_n * 32 + (lane & 7) + ((lane >> 4) << 3);  // + g*16
    const int b_kc  = (lane >> 3) & 1;

    const int NT = K1 / G1_BK;   // 16 chunks
    int sidx = 0;
    for (int t = 0; t < NT; t++) {
        if (t == NT - 1) cp_wait0(); else cp_wait1();
        __syncthreads();

        if (t + 2 < NT) {
            int s2 = sidx + 2; if (s2 >= 3) s2 -= 3;
            load_stage(t + 2, s2);
        }

        const uint32_t stg = sb + sidx * G1_STAGE;
#pragma unroll
        for (int ks = 0; ks < 4; ks++) {             // k32 steps (32B each)
            uint32_t b[4][2];
#pragma unroll
            for (int g = 0; g < 2; g++) {            // 2 x4 loads -> 4 n-tiles
                uint32_t addr = stg + G1_B_OFF
                    + swz((uint32_t)((b_row + g * 16) * 128
                                     + (ks * 2 + b_kc) * 16));
                ldsm4(b[2 * g][0], b[2 * g][1], b[2 * g + 1][0], b[2 * g + 1][1],
                      addr);
            }
            uint32_t a[4][4];
            // hi limb
#pragma unroll
            for (int mt = 0; mt < 4; mt++) {
                uint32_t addr = stg + G1_A0_OFF
                    + swz((uint32_t)((a_row + mt * 16) * 128
                                     + (ks * 2 + a_kc) * 16));
                ldsm4(a[mt][0], a[mt][1], a[mt][2], a[mt][3], addr);
            }
#pragma unroll
            for (int mt = 0; mt < 4; mt++)
#pragma unroll
                for (int nt = 0; nt < 4; nt++)
                    mma_s8(chi[mt][nt], a[mt], b[nt]);
            // lo limb
#pragma unroll
            for (int mt = 0; mt < 4; mt++) {
                uint32_t addr = stg + G1_A1_OFF
                    + swz((uint32_t)((a_row + mt * 16) * 128
                                     + (ks * 2 + a_kc) * 16));
                ldsm4(a[mt][0], a[mt][1], a[mt][2], a[mt][3], addr);
            }
#pragma unroll
            for (int mt = 0; mt < 4; mt++)
#pragma unroll
                for (int nt = 0; nt < 4; nt++)
                    mma_s8(clo[mt][nt], a[mt], b[nt]);
        }
        sidx = sidx + 1; if (sidx >= 3) sidx -= 3;
    }

    // ---- epilogue: v = hi*256+lo = round(4096*x)@proj (exact int) ----
    const int er = m0 + warp_m * 64 + (lane >> 2);
    const int ec = n0 + warp_n * 32 + 2 * (lane & 3);

    unsigned nflag = 0;
    unsigned fl[16];
#pragma unroll
    for (int mt = 0; mt < 4; mt++) {
#pragma unroll
        for (int nt = 0; nt < 4; nt++) {
            int v0 = chi[mt][nt][0] * 256 + clo[mt][nt][0];
            int v1 = chi[mt][nt][1] * 256 + clo[mt][nt][1];
            int v2 = chi[mt][nt][2] * 256 + clo[mt][nt][2];
            int v3 = chi[mt][nt][3] * 256 + clo[mt][nt][3];
            bool s0 = v0 >= 0, s1 = v1 >= 0, s2 = v2 >= 0, s3 = v3 >= 0;
            const int r0r = er + mt * 16;
            const int cc  = ec + nt * 8;
            if (abs(v0) < ITAU && nflag < 16)
                fl[nflag++] = ((unsigned)r0r << 13) | (unsigned)cc;
            if (abs(v1) < ITAU && nflag < 16)
                fl[nflag++] = ((unsigned)r0r << 13) | (unsigned)(cc + 1);
            if (abs(v2) < ITAU && nflag < 16)
                fl[nflag++] = ((unsigned)(r0r + 8) << 13) | (unsigned)cc;
            if (abs(v3) < ITAU && nflag < 16)
                fl[nflag++] = ((unsigned)(r0r + 8) << 13) | (unsigned)(cc + 1);
            size_t o = (size_t)r0r * N1 + cc;
            *(float2*)(hv + o) = make_float2(s0 ? 1.0f : -1.0f,
                                             s1 ? 1.0f : -1.0f);
            *(float2*)(hv + o + 8 * N1) = make_float2(s2 ? 1.0f : -1.0f,
                                                      s3 ? 1.0f : -1.0f);
            *(char2*)(g_hvb8 + o) =
                make_char2(s0 ? 1 : -1, s1 ? 1 : -1);
            *(char2*)(g_hvb8 + o + 8 * N1) =
                make_char2(s2 ? 1 : -1, s3 ? 1 : -1);
        }
    }

    // warp-aggregated worklist append
    unsigned any = __ballot_sync(0xffffffffu, nflag > 0);
    if (any) {
        unsigned off = nflag;
#pragma unroll
        for (int d = 1; d < 32; d <<= 1) {
            unsigned t2 = __shfl_up_sync(0xffffffffu, off, d);
            if (lane >= d) off += t2;
        }
        unsigned tot = __shfl_sync(0xffffffffu, off, 31);
        unsigned base = 0;
        if (lane == 31) base = atomicAdd(&g_wl_count, tot);
        base = __shfl_sync(0xffffffffu, base, 31);
        unsigned my = base + off - nflag;
        for (unsigned i = 0; i < nflag; i++)
            if (my + i < WL_CAP) g_wl[my + i] = fl[i];
    }
}

// ---------------------------------------------------------------------------
// Fixup: recompute borderline elements with the reference's exact rounding
// (single sequential ascending-k fp32 FMA chain). Updates hv AND g_hvb8.
// ---------------------------------------------------------------------------
__global__ __launch_bounds__(256) void fixup_kernel(const float* __restrict__ x,
                                                    float* __restrict__ hv)
{
    unsigned total = g_wl_count;
    if (total > WL_CAP) total = WL_CAP;
    for (unsigned i = blockIdx.x * 256 + threadIdx.x; i < total;
         i += gridDim.x * 256) {
        unsigned e = g_wl[i];
        int row = (int)(e >> 13);
        int col = (int)(e & 8191u);
        const float* xr = x + (size_t)row * K1;
        const __nv_bfloat16* pc = g_projT + (size_t)col * K1;
        float s = 0.0f;
        for (int k = 0; k < K1; k += 8) {
            float4 xa = *(const float4*)(xr + k);
            float4 xb = *(const float4*)(xr + k + 4);
            float p0 = __bfloat162float(pc[k + 0]);
            float p1 = __bfloat162float(pc[k + 1]);
            float p2 = __bfloat162float(pc[k + 2]);
            float p3 = __bfloat162float(pc[k + 3]);
            float p4 = __bfloat162float(pc[k + 4]);
            float p5 = __bfloat162float(pc[k + 5]);
            float p6 = __bfloat162float(pc[k + 6]);
            float p7 = __bfloat162float(pc[k + 7]);
            s = fmaf(xa.x, p0, s); s = fmaf(xa.y, p1, s);
            s = fmaf(xa.z, p2, s); s = fmaf(xa.w, p3, s);
            s = fmaf(xb.x, p4, s); s = fmaf(xb.y, p5, s);
            s = fmaf(xb.z, p6, s); s = fmaf(xb.w, p7, s);
        }
        bool pos = (s >= 0.0f);
        hv[(size_t)row * N1 + col] = pos ? 1.0f : -1.0f;
        g_hvb8[(size_t)row * N1 + col] = pos ? 1 : -1;
    }
}

// ---------------------------------------------------------------------------
// GEMM2 via s8 IMMA: scores = hv_bin @ class_hv (exact s32 -> fp32).
// CTA 128x256xK128; 8 warps (2m x 4n), warp tile 64x64; 3-stage cp.async.
// ---------------------------------------------------------------------------
__global__ __launch_bounds__(256, 1) void gemm2_imma(float* __restrict__ scores)
{
    extern __shared__ char smem[];
    const uint32_t sb = smem_u32(smem);
    const int tid = threadIdx.x, wid = tid >> 5, lane = tid & 31;
    const int warp_m = wid >> 2;
    const int warp_n = wid & 3;
    const int m0 = blockIdx.y * G2_BM;
    const int n0 = blockIdx.x * G2_BN;

    int c[4][8][4];
#pragma unroll
    for (int i = 0; i < 4; i++)
#pragma unroll
        for (int j = 0; j < 8; j++)
#pragma unroll
            for (int q = 0; q < 4; q++) c[i][j][q] = 0;

    auto load_stage = [&](int chunk, int s) {
        const size_t k0 = (size_t)chunk * G2_BK;
        const char* ab = (const char*)g_hvb8 + (size_t)m0 * N1 + k0;
#pragma unroll
        for (int i = 0; i < 4; i++) {
            int idx = tid + i * 256;                 // 0..1023
            int r = idx >> 3, cc = idx & 7;
            cp_async16(sb + s * G2_STAGE + G2_A_OFF
                           + swz((uint32_t)(r * 128 + cc * 16)),
                       ab + (size_t)r * N1 + cc * 16);
        }
        const char* bb = (const char*)g_chvT8 + (size_t)n0 * N1 + k0;
#pragma unroll
        for (int i = 0; i < 8; i++) {
            int idx = tid + i * 256;                 // 0..2047
            int r = idx >> 3, cc = idx & 7;
            cp_async16(sb + s * G2_STAGE + G2_B_OFF
                           + swz((uint32_t)(r * 128 + cc * 16)),
                       bb + (size_t)r * N1 + cc * 16);
        }
        cp_commit();
    };

    load_stage(0, 0);
    load_stage(1, 1);

    const int a_row = warp_m * 64 + (lane & 15);
    const int a_kc  = (lane >> 4);
    const int b_row = warp_n * 64 + (lane & 7) + ((lane >> 4) << 3);
    const int b_kc  = (lane >> 3) & 1;

    const int NT = N1 / G2_BK;   // 64 chunks
    int sidx = 0;
    for (int t = 0; t < NT; t++) {
        if (t == NT - 1) cp_wait0(); else cp_wait1();
        __syncthreads();

        if (t + 2 < NT) {
            int s2 = sidx + 2; if (s2 >= 3) s2 -= 3;
            load_stage(t + 2, s2);
        }

        const uint32_t stg = sb + sidx * G2_STAGE;
#pragma unroll
        for (int ks = 0; ks < 4; ks++) {
            uint32_t b[8][2];
#pragma unroll
            for (int g = 0; g < 4; g++) {
                uint32_t addr = stg + G2_B_OFF
                    + swz((uint32_t)((b_row + g * 16) * 128
                                     + (ks * 2 + b_kc) * 16));
                ldsm4(b[2 * g][0], b[2 * g][1], b[2 * g + 1][0], b[2 * g + 1][1],
                      addr);
            }
            uint32_t a[4][4];
#pragma unroll
            for (int mt = 0; mt < 4; mt++) {
                uint32_t addr = stg + G2_A_OFF
                    + swz((uint32_t)((a_row + mt * 16) * 128
                                     + (ks * 2 + a_kc) * 16));
                ldsm4(a[mt][0], a[mt][1], a[mt][2], a[mt][3], addr);
            }
#pragma unroll
            for (int mt = 0; mt < 4; mt++)
#pragma unroll
                for (int nt = 0; nt < 8; nt++)
                    mma_s8(c[mt][nt], a[mt], b[nt]);
        }
        sidx = sidx + 1; if (sidx >= 3) sidx -= 3;
    }

    // ---- epilogue: exact int -> fp32 stores, guard col < NC ----
    const int er = m0 + warp_m * 64 + (lane >> 2);
    const int ec = n0 + warp_n * 64 + 2 * (lane & 3);
#pragma unroll
    for (int mt = 0; mt < 4; mt++) {
#pragma unroll
        for (int nt = 0; nt < 8; nt++) {
            const int cc = ec + nt * 8;
            if (cc < NC) {
                const int r0r = er + mt * 16;
                *(float2*)(scores + (size_t)r0r * NC + cc) =
                    make_float2((float)c[mt][nt][0], (float)c[mt][nt][1]);
                *(float2*)(scores + (size_t)(r0r + 8) * NC + cc) =
                    make_float2((float)c[mt][nt][2], (float)c[mt][nt][3]);
            }
        }
    }
}

// ---------------------------------------------------------------------------
extern "C" void kernel_launch(void* const* d_in, const int* in_sizes, int n_in,
                              void* d_out, int out_size)
{
    const float* x    = (const float*)d_in[0];   // [16384, 2048]
    const float* proj = (const float*)d_in[1];   // [2048, 8192]
    const float* chv  = (const float*)d_in[2];   // [8192, 1000]

    float* scores = (float*)d_out;                       // [16384, 1000]
    float* hv     = scores + (size_t)MB * NC;            // [16384, 8192]

    cudaFuncSetAttribute(gemm1_imma, cudaFuncAttributeMaxDynamicSharedMemorySize,
                         G1_SMEM);
    cudaFuncSetAttribute(gemm2_imma, cudaFuncAttributeMaxDynamicSharedMemorySize,
                         G2_SMEM);

    zero_count_kernel<<<1, 1>>>();
    prep_split8<<<(unsigned)((size_t)MB * K1 / 1024), 256>>>(x);
    prep_projT_k<<<dim3(N1 / 32, K1 / 32), dim3(32, 8)>>>(proj);
    prep_chvT8<<<dim3(NCP / 32, N1 / 32), dim3(32, 8)>>>(chv);

    gemm1_imma<<<dim3(N1 / G1_BN, MB / G1_BM), 256, G1_SMEM>>>(hv);

    fixup_kernel<<<1024, 256>>>(x, hv);

    gemm2_imma<<<dim3(NCP / G2_BN, MB / G2_BM), 256, G2_SMEM>>>(scores);
}

// round 15
// speedup vs baseline: 3.1977x; 3.1977x over previous
#include <cuda_runtime.h>
#include <cuda_bf16.h>
#include <cstdint>

// Problem dims
#define MB   16384   // batch
#define K1   2048    // IN_DIM
#define N1   8192    // HV_DIM
#define NC   1000    // NUM_CLASSES
#define NCP  1024    // padded classes

// GEMM tile config (mma.sync path, BK=64 -> 128B SW128 rows)
#define BM   128
#define BN   256
#define BK   64

// GEMM1 smem: 2 A-limbs (16KB each) + B (32KB) per stage, 3 stages
#define G1_A_OFF(sp) ((sp) * 16384)
#define G1_B_OFF     32768
#define G1_STAGE_BYTES  65536
#define G1_SMEM   (3 * G1_STAGE_BYTES)       // 196608

// GEMM2 smem: A (16KB) + B (32KB) per stage, 3 stages
#define G2_A_OFF     0
#define G2_B_OFF     16384
#define G2_STAGE_BYTES  49152
#define G2_SMEM   (3 * G2_STAGE_BYTES)       // 147456

#define TAU     0.02f                        // borderline threshold (50 sigma)
#define WL_CAP  (1u << 22)                   // 4M worklist entries

// -------------------- device scratch (allocation-free rule) -----------------
__device__ __nv_bfloat16 g_xhi [(size_t)MB * K1];
__device__ __nv_bfloat16 g_xmid[(size_t)MB * K1];
__device__ __nv_bfloat16 g_projT[(size_t)N1 * K1];    // [N1, K1] K-major
__device__ __nv_bfloat16 g_hvb [(size_t)MB * N1];     // hv_bin as bf16
__device__ __nv_bfloat16 g_chvT[(size_t)NCP * N1];    // [NCP, N1] K-major, padded
__device__ unsigned g_wl[WL_CAP];                     // borderline worklist
__device__ unsigned g_wl_count;

// -------------------- PTX helpers (baseline ISA only, sm_80+) ---------------
__device__ __forceinline__ uint32_t smem_u32(const void* p) {
    uint32_t a;
    asm("{ .reg .u64 t; cvta.to.shared.u64 t, %1; cvt.u32.u64 %0, t; }"
        : "=r"(a) : "l"(p));
    return a;
}
__device__ __forceinline__ void cp_async16(uint32_t dst, const void* src) {
    asm volatile("cp.async.cg.shared.global [%0], [%1], 16;\n"
                 :: "r"(dst), "l"(src) : "memory");
}
__device__ __forceinline__ void cp_commit() {
    asm volatile("cp.async.commit_group;" ::: "memory");
}
__device__ __forceinline__ void cp_wait1() {
    asm volatile("cp.async.wait_group 1;" ::: "memory");
}
__device__ __forceinline__ void cp_wait0() {
    asm volatile("cp.async.wait_group 0;" ::: "memory");
}
__device__ __forceinline__ void ldsm4(uint32_t& r0, uint32_t& r1, uint32_t& r2,
                                      uint32_t& r3, uint32_t addr) {
    asm volatile("ldmatrix.sync.aligned.m8n8.x4.shared.b16 {%0,%1,%2,%3}, [%4];"
                 : "=r"(r0), "=r"(r1), "=r"(r2), "=r"(r3) : "r"(addr));
}
__device__ __forceinline__ void mma_bf16(float* c, const uint32_t* a,
                                         const uint32_t* b) {
    asm volatile(
        "mma.sync.aligned.m16n8k16.row.col.f32.bf16.bf16.f32 "
        "{%0,%1,%2,%3}, {%4,%5,%6,%7}, {%8,%9}, {%0,%1,%2,%3};"
        : "+f"(c[0]), "+f"(c[1]), "+f"(c[2]), "+f"(c[3])
        : "r"(a[0]), "r"(a[1]), "r"(a[2]), "r"(a[3]), "r"(b[0]), "r"(b[1]));
}
// SW128: byte_off ^ ((byte_off>>3)&0x70), 16B-chunk granular
__device__ __forceinline__ uint32_t swz(uint32_t off) {
    return off ^ ((off >> 3) & 0x70);
}

// ---------------------------------------------------------------------------
__global__ void zero_count_kernel() { g_wl_count = 0; }

// ---------------------------------------------------------------------------
// prep: 2-way bf16 split of x (hi+mid captures 16 mantissa bits)
// ---------------------------------------------------------------------------
__global__ __launch_bounds__(256) void prep_split(const float* __restrict__ x)
{
    size_t i4 = ((size_t)blockIdx.x * 256 + threadIdx.x) * 4;
    float4 v = *(const float4*)(x + i4);
    const float f[4] = {v.x, v.y, v.z, v.w};
    __nv_bfloat16 h[4], m[4];
#pragma unroll
    for (int e = 0; e < 4; e++) {
        float a = f[e];
        __nv_bfloat16 hi = __float2bfloat16_rn(a);
        float r1 = a - __bfloat162float(hi);
        h[e] = hi; m[e] = __float2bfloat16_rn(r1);
    }
    ((__nv_bfloat162*)(g_xhi  + i4))[0] = __nv_bfloat162(h[0], h[1]);
    ((__nv_bfloat162*)(g_xhi  + i4))[1] = __nv_bfloat162(h[2], h[3]);
    ((__nv_bfloat162*)(g_xmid + i4))[0] = __nv_bfloat162(m[0], m[1]);
    ((__nv_bfloat162*)(g_xmid + i4))[1] = __nv_bfloat162(m[2], m[3]);
}

// ---------------------------------------------------------------------------
// prep: projT[n][k] = bf16(proj[k][n])  (exact, proj is +/-1)
// ---------------------------------------------------------------------------
__global__ __launch_bounds__(256) void prep_projT(const float* __restrict__ proj)
{
    __shared__ float t[32][33];
    const int n0 = blockIdx.x * 32, k0 = blockIdx.y * 32;
    const int tx = threadIdx.x, ty = threadIdx.y;   // (32, 8)
#pragma unroll
    for (int i = 0; i < 4; i++)
        t[ty + i * 8][tx] = proj[(size_t)(k0 + ty + i * 8) * N1 + n0 + tx];
    __syncthreads();
#pragma unroll
    for (int i = 0; i < 4; i++) {
        int r = ty + i * 8;
        g_projT[(size_t)(n0 + r) * K1 + k0 + tx] = __float2bfloat16_rn(t[tx][r]);
    }
}

// ---------------------------------------------------------------------------
// prep: chvT[c][k] = bf16(class_hv[k][c]), zero-padded classes 1000..1023
// ---------------------------------------------------------------------------
__global__ __launch_bounds__(256) void prep_chvT(const float* __restrict__ chv)
{
    __shared__ float t[32][33];
    const int c0 = blockIdx.x * 32, k0 = blockIdx.y * 32;
    const int tx = threadIdx.x, ty = threadIdx.y;   // (32, 8)
#pragma unroll
    for (int i = 0; i < 4; i++) {
        int c = c0 + tx;
        t[ty + i * 8][tx] = (c < NC)
            ? chv[(size_t)(k0 + ty + i * 8) * NC + c] : 0.0f;
    }
    __syncthreads();
#pragma unroll
    for (int i = 0; i < 4; i++) {
        int r = ty + i * 8;     // class within tile
        g_chvT[(size_t)(c0 + r) * N1 + k0 + tx] = __float2bfloat16_rn(t[tx][r]);
    }
}

// ---------------------------------------------------------------------------
// GEMM1 via mma.sync bf16 (2-limb split), sign epilogue -> hv fp32 + hvb bf16
// + borderline flagging. 128x256x64 CTA tile, 8 warps, 3-stage cp.async.
// ---------------------------------------------------------------------------
__global__ __launch_bounds__(256, 1) void gemm1_mma(float* __restrict__ hv)
{
    extern __shared__ char smem[];
    const uint32_t sb = smem_u32(smem);
    const int tid = threadIdx.x, wid = tid >> 5, lane = tid & 31;
    const int warp_m = wid >> 2;
    const int warp_n = wid & 3;
    const int m0 = blockIdx.y * BM;
    const int n0 = blockIdx.x * BN;

    float c[4][8][4];
#pragma unroll
    for (int i = 0; i < 4; i++)
#pragma unroll
        for (int j = 0; j < 8; j++)
#pragma unroll
            for (int q = 0; q < 4; q++) c[i][j][q] = 0.0f;

    const __nv_bfloat16* const xs[2] = {g_xhi, g_xmid};

    auto load_stage = [&](int chunk, int s) {
        const size_t k0 = (size_t)chunk * BK;
#pragma unroll
        for (int sp = 0; sp < 2; sp++) {
            const char* base = (const char*)xs[sp] + ((size_t)m0 * K1 + k0) * 2;
#pragma unroll
            for (int i = 0; i < 4; i++) {
                int idx = tid + i * 256;
                int r = idx >> 3, cc = idx & 7;
                uint32_t dst = sb + s * G1_STAGE_BYTES + G1_A_OFF(sp)
                             + swz((uint32_t)(r * 128 + cc * 16));
                cp_async16(dst, base + (size_t)r * (K1 * 2) + cc * 16);
            }
        }
        const char* bb = (const char*)g_projT + ((size_t)n0 * K1 + k0) * 2;
#pragma unroll
        for (int i = 0; i < 8; i++) {
            int idx = tid + i * 256;
            int r = idx >> 3, cc = idx & 7;
            uint32_t dst = sb + s * G1_STAGE_BYTES + G1_B_OFF
                         + swz((uint32_t)(r * 128 + cc * 16));
            cp_async16(dst, bb + (size_t)r * (K1 * 2) + cc * 16);
        }
        cp_commit();
    };

    load_stage(0, 0);
    load_stage(1, 1);

    const int a_row = warp_m * 64 + (lane & 15);
    const int a_kc  = (lane >> 4);
    const int b_row = warp_n * 64 + (lane & 7) + ((lane >> 4) << 3);
    const int b_kc  = (lane >> 3) & 1;

    int sidx = 0;                         // buffer holding chunk t
    for (int t = 0; t < 32; t++) {
        if (t == 31) cp_wait0(); else cp_wait1();
        __syncthreads();                  // single barrier per chunk

        if (t + 2 < 32) {
            int s2 = sidx + 2; if (s2 >= 3) s2 -= 3;
            load_stage(t + 2, s2);
        }

        const uint32_t stg = sb + sidx * G1_STAGE_BYTES;
#pragma unroll
        for (int ks = 0; ks < 4; ks++) {
            uint32_t b[8][2];
#pragma unroll
            for (int g = 0; g < 4; g++) {
                uint32_t addr = stg + G1_B_OFF
                    + swz((uint32_t)((b_row + g * 16) * 128
                                     + (ks * 2 + b_kc) * 16));
                ldsm4(b[2 * g][0], b[2 * g][1], b[2 * g + 1][0], b[2 * g + 1][1],
                      addr);
            }
#pragma unroll
            for (int sp = 0; sp < 2; sp++) {
                uint32_t a[4][4];
#pragma unroll
                for (int mt = 0; mt < 4; mt++) {
                    uint32_t addr = stg + G1_A_OFF(sp)
                        + swz((uint32_t)((a_row + mt * 16) * 128
                                         + (ks * 2 + a_kc) * 16));
                    ldsm4(a[mt][0], a[mt][1], a[mt][2], a[mt][3], addr);
                }
#pragma unroll
                for (int mt = 0; mt < 4; mt++)
#pragma unroll
                    for (int nt = 0; nt < 8; nt++)
                        mma_bf16(c[mt][nt], a[mt], b[nt]);
            }
        }
        sidx = sidx + 1; if (sidx >= 3) sidx -= 3;
    }

    // ---- epilogue: sign -> fp32 hv + bf16 hvb + borderline flagging ----
    const int er = m0 + warp_m * 64 + (lane >> 2);
    const int ec = n0 + warp_n * 64 + 2 * (lane & 3);

    unsigned nflag = 0;
    unsigned fl[16];
    const __nv_bfloat16 pb = __float2bfloat16_rn(1.0f);
    const __nv_bfloat16 nb = __float2bfloat16_rn(-1.0f);
#pragma unroll
    for (int mt = 0; mt < 4; mt++) {
#pragma unroll
        for (int nt = 0; nt < 8; nt++) {
            bool s0 = c[mt][nt][0] >= 0.0f;
            bool s1 = c[mt][nt][1] >= 0.0f;
            bool s2 = c[mt][nt][2] >= 0.0f;
            bool s3 = c[mt][nt][3] >= 0.0f;
            float2 v0 = make_float2(s0 ? 1.0f : -1.0f, s1 ? 1.0f : -1.0f);
            float2 v1 = make_float2(s2 ? 1.0f : -1.0f, s3 ? 1.0f : -1.0f);
            const int r0r = er + mt * 16;
            const int cc  = ec + nt * 8;
            if (fabsf(c[mt][nt][0]) < TAU && nflag < 16)
                fl[nflag++] = ((unsigned)r0r << 13) | (unsigned)cc;
            if (fabsf(c[mt][nt][1]) < TAU && nflag < 16)
                fl[nflag++] = ((unsigned)r0r << 13) | (unsigned)(cc + 1);
            if (fabsf(c[mt][nt][2]) < TAU && nflag < 16)
                fl[nflag++] = ((unsigned)(r0r + 8) << 13) | (unsigned)cc;
            if (fabsf(c[mt][nt][3]) < TAU && nflag < 16)
                fl[nflag++] = ((unsigned)(r0r + 8) << 13) | (unsigned)(cc + 1);
            size_t o = (size_t)r0r * N1 + cc;
            *(float2*)(hv + o)          = v0;
            *(float2*)(hv + o + 8 * N1) = v1;
            *(__nv_bfloat162*)(g_hvb + o) =
                __nv_bfloat162(s0 ? pb : nb, s1 ? pb : nb);
            *(__nv_bfloat162*)(g_hvb + o + 8 * N1) =
                __nv_bfloat162(s2 ? pb : nb, s3 ? pb : nb);
        }
    }

    // warp-aggregated worklist append
    unsigned any = __ballot_sync(0xffffffffu, nflag > 0);
    if (any) {
        unsigned off = nflag;
#pragma unroll
        for (int d = 1; d < 32; d <<= 1) {
            unsigned t2 = __shfl_up_sync(0xffffffffu, off, d);
            if (lane >= d) off += t2;
        }
        unsigned tot = __shfl_sync(0xffffffffu, off, 31);
        unsigned base = 0;
        if (lane == 31) base = atomicAdd(&g_wl_count, tot);
        base = __shfl_sync(0xffffffffu, base, 31);
        unsigned my = base + off - nflag;
        for (unsigned i = 0; i < nflag; i++)
            if (my + i < WL_CAP) g_wl[my + i] = fl[i];
    }
}

// ---------------------------------------------------------------------------
// Fixup: recompute borderline elements with the reference's exact rounding
// (single sequential ascending-k fp32 FMA chain). Updates hv AND g_hvb.
// Vectorized 16B loads of the proj column; FMA order unchanged (bitwise).
// ---------------------------------------------------------------------------
__global__ __launch_bounds__(256) void fixup_kernel(const float* __restrict__ x,
                                                    float* __restrict__ hv)
{
    unsigned total = g_wl_count;
    if (total > WL_CAP) total = WL_CAP;
    for (unsigned i = blockIdx.x * 256 + threadIdx.x; i < total;
         i += gridDim.x * 256) {
        unsigned e = g_wl[i];
        int row = (int)(e >> 13);
        int col = (int)(e & 8191u);
        const float* xr = x + (size_t)row * K1;
        const __nv_bfloat16* pc = g_projT + (size_t)col * K1;
        float s = 0.0f;
        for (int k = 0; k < K1; k += 8) {
            float4 xa = *(const float4*)(xr + k);
            float4 xb = *(const float4*)(xr + k + 4);
            uint4 praw = *(const uint4*)(pc + k);   // 8 bf16
            __nv_bfloat162 q0 = *(__nv_bfloat162*)&praw.x;
            __nv_bfloat162 q1 = *(__nv_bfloat162*)&praw.y;
            __nv_bfloat162 q2 = *(__nv_bfloat162*)&praw.z;
            __nv_bfloat162 q3 = *(__nv_bfloat162*)&praw.w;
            s = fmaf(xa.x, __bfloat162float(q0.x), s);
            s = fmaf(xa.y, __bfloat162float(q0.y), s);
            s = fmaf(xa.z, __bfloat162float(q1.x), s);
            s = fmaf(xa.w, __bfloat162float(q1.y), s);
            s = fmaf(xb.x, __bfloat162float(q2.x), s);
            s = fmaf(xb.y, __bfloat162float(q2.y), s);
            s = fmaf(xb.z, __bfloat162float(q3.x), s);
            s = fmaf(xb.w, __bfloat162float(q3.y), s);
        }
        float v = (s >= 0.0f) ? 1.0f : -1.0f;
        hv[(size_t)row * N1 + col] = v;
        g_hvb[(size_t)row * N1 + col] = __float2bfloat16_rn(v);
    }
}

// ---------------------------------------------------------------------------
// GEMM2 via mma.sync bf16: scores = hv_bin @ class_hv.
// Operands +/-1 (exact bf16); fp32 accumulation of integers |s|<=8192 is
// EXACT in any order. 128x256x64 tile, K=8192, 3-stage cp.async.
// ---------------------------------------------------------------------------
__global__ __launch_bounds__(256, 1) void gemm2_mma(float* __restrict__ scores)
{
    extern __shared__ char smem[];
    const uint32_t sb = smem_u32(smem);
    const int tid = threadIdx.x, wid = tid >> 5, lane = tid & 31;
    const int warp_m = wid >> 2;
    const int warp_n = wid & 3;
    const int m0 = blockIdx.y * BM;
    const int n0 = blockIdx.x * BN;

    float c[4][8][4];
#pragma unroll
    for (int i = 0; i < 4; i++)
#pragma unroll
        for (int j = 0; j < 8; j++)
#pragma unroll
            for (int q = 0; q < 4; q++) c[i][j][q] = 0.0f;

    auto load_stage = [&](int chunk, int s) {
        const size_t k0 = (size_t)chunk * BK;
        const char* ab = (const char*)g_hvb + ((size_t)m0 * N1 + k0) * 2;
#pragma unroll
        for (int i = 0; i < 4; i++) {
            int idx = tid + i * 256;
            int r = idx >> 3, cc = idx & 7;
            uint32_t dst = sb + s * G2_STAGE_BYTES + G2_A_OFF
                         + swz((uint32_t)(r * 128 + cc * 16));
            cp_async16(dst, ab + (size_t)r * (N1 * 2) + cc * 16);
        }
        const char* bb = (const char*)g_chvT + ((size_t)n0 * N1 + k0) * 2;
#pragma unroll
        for (int i = 0; i < 8; i++) {
            int idx = tid + i * 256;
            int r = idx >> 3, cc = idx & 7;
            uint32_t dst = sb + s * G2_STAGE_BYTES + G2_B_OFF
                         + swz((uint32_t)(r * 128 + cc * 16));
            cp_async16(dst, bb + (size_t)r * (N1 * 2) + cc * 16);
        }
        cp_commit();
    };

    load_stage(0, 0);
    load_stage(1, 1);

    const int a_row = warp_m * 64 + (lane & 15);
    const int a_kc  = (lane >> 4);
    const int b_row = warp_n * 64 + (lane & 7) + ((lane >> 4) << 3);
    const int b_kc  = (lane >> 3) & 1;

    const int NT = N1 / BK;   // 128 k-chunks
    int sidx = 0;
    for (int t = 0; t < NT; t++) {
        if (t == NT - 1) cp_wait0(); else cp_wait1();
        __syncthreads();

        if (t + 2 < NT) {
            int s2 = sidx + 2; if (s2 >= 3) s2 -= 3;
            load_stage(t + 2, s2);
        }

        const uint32_t stg = sb + sidx * G2_STAGE_BYTES;
#pragma unroll
        for (int ks = 0; ks < 4; ks++) {
            uint32_t b[8][2];
#pragma unroll
            for (int g = 0; g < 4; g++) {
                uint32_t addr = stg + G2_B_OFF
                    + swz((uint32_t)((b_row + g * 16) * 128
                                     + (ks * 2 + b_kc) * 16));
                ldsm4(b[2 * g][0], b[2 * g][1], b[2 * g + 1][0], b[2 * g + 1][1],
                      addr);
            }
            uint32_t a[4][4];
#pragma unroll
            for (int mt = 0; mt < 4; mt++) {
                uint32_t addr = stg + G2_A_OFF
                    + swz((uint32_t)((a_row + mt * 16) * 128
                                     + (ks * 2 + a_kc) * 16));
                ldsm4(a[mt][0], a[mt][1], a[mt][2], a[mt][3], addr);
            }
#pragma unroll
            for (int mt = 0; mt < 4; mt++)
#pragma unroll
                for (int nt = 0; nt < 8; nt++)
                    mma_bf16(c[mt][nt], a[mt], b[nt]);
        }
        sidx = sidx + 1; if (sidx >= 3) sidx -= 3;
    }

    // ---- epilogue: store raw fp32 (exact integers), guard col < NC ----
    const int er = m0 + warp_m * 64 + (lane >> 2);
    const int ec = n0 + warp_n * 64 + 2 * (lane & 3);
#pragma unroll
    for (int mt = 0; mt < 4; mt++) {
#pragma unroll
        for (int nt = 0; nt < 8; nt++) {
            const int cc = ec + nt * 8;
            if (cc < NC) {
                const int r0r = er + mt * 16;
                *(float2*)(scores + (size_t)r0r * NC + cc) =
                    make_float2(c[mt][nt][0], c[mt][nt][1]);
                *(float2*)(scores + (size_t)(r0r + 8) * NC + cc) =
                    make_float2(c[mt][nt][2], c[mt][nt][3]);
            }
        }
    }
}

// ---------------------------------------------------------------------------
extern "C" void kernel_launch(void* const* d_in, const int* in_sizes, int n_in,
                              void* d_out, int out_size)
{
    const float* x    = (const float*)d_in[0];   // [16384, 2048]
    const float* proj = (const float*)d_in[1];   // [2048, 8192]
    const float* chv  = (const float*)d_in[2];   // [8192, 1000]

    float* scores = (float*)d_out;                       // [16384, 1000]
    float* hv     = scores + (size_t)MB * NC;            // [16384, 8192]

    cudaFuncSetAttribute(gemm1_mma, cudaFuncAttributeMaxDynamicSharedMemorySize,
                         G1_SMEM);
    cudaFuncSetAttribute(gemm2_mma, cudaFuncAttributeMaxDynamicSharedMemorySize,
                         G2_SMEM);

    zero_count_kernel<<<1, 1>>>();
    prep_split<<<(unsigned)((size_t)MB * K1 / 1024), 256>>>(x);
    prep_projT<<<dim3(N1 / 32, K1 / 32), dim3(32, 8)>>>(proj);
    prep_chvT<<<dim3(NCP / 32, N1 / 32), dim3(32, 8)>>>(chv);

    gemm1_mma<<<dim3(N1 / BN, MB / BM), 256, G1_SMEM>>>(hv);

    fixup_kernel<<<1024, 256>>>(x, hv);

    gemm2_mma<<<dim3(NCP / BN, MB / BM), 256, G2_SMEM>>>(scores);
}